// round 14
// baseline (speedup 1.0000x reference)
#include <cuda_runtime.h>

// TemporalDecay: out = h + (1-M)*gamma*(h_fwd - h), gamma = exp(-relu(delta*W + b))
// h_fwd[b,t,j] = h[b, t-(delta-1), j], delta in {1..4} clamped to t+1, d = j % 64.
//
// R13 = R10 (d-pair per thread, 8 outputs via float2, uniform delta/M per d,
// stride-1 predicated gathers, batched loads for MLP) with:
//  * delta/M on DEFAULT cache policy: inputs (h+delta+M = 101MB) fit L2 (126MB)
//    and persist across graph replays; __ldcs was evicting them and forcing
//    ~34MB of avoidable DRAM reads per replay. Also shortens the
//    delta -> gather-address -> gather dependent chain to L2 latency.
//  * out keeps __stcs (write-once, never read: stay out of L2's hot set).
//  * __launch_bounds__(256,7): regs 40 -> 36, 7 blocks/SM, occ ~68% at the
//    SAME per-thread MLP (R11's occupancy-vs-MLP trade avoided).

#define B_    32
#define T_    2048
#define D_    64
#define KD_   256
#define TPB   256
#define NTHR  (B_ * T_ * D_ / 2)   // 2,097,152 threads (one d-pair each)

__global__ __launch_bounds__(TPB, 7)
void temporal_decay_kernel(const float*  __restrict__ h,
                           const float2* __restrict__ h2,
                           const float2* __restrict__ dlt2,
                           const float2* __restrict__ m2,
                           const float2* __restrict__ w2,
                           const float2* __restrict__ b2,
                           float2* __restrict__ out2)
{
    const int i   = blockIdx.x * TPB + threadIdx.x;
    const int p   = i & 31;              // d-pair index: d = 2p
    const int row = i >> 5;              // b*T + t

    // ---- phase 1: small operands -> coefs + gather state ----
    const float2 df = dlt2[(row << 5) + p];
    const float2 mf = m2[(row << 5) + p];

    const int dix = (int)df.x, diy = (int)df.y;
    const float ax = 1.0f - mf.x, ay = 1.0f - mf.y;
    const bool needx = (mf.x == 0.0f) && (dix > 1);
    const bool needy = (mf.y == 0.0f) && (diy > 1);

    const int base   = (row << 8) + (p << 1);          // scalar index, k=0, lane d
    const int gbasex = base - ((dix - 1) << 8);        // gather bases
    const int gbasey = base + 1 - ((diy - 1) << 8);

    // coef_k = (1-m) * min(exp(-(d*W+b)), 1)
    float cx[4], cy[4];
    #pragma unroll
    for (int k = 0; k < 4; ++k) {
        const float2 ww = w2[(k << 5) + p];
        const float2 bb = b2[(k << 5) + p];
        cx[k] = ax * fminf(__expf(-fmaf(df.x, ww.x, bb.x)), 1.0f);
        cy[k] = ay * fminf(__expf(-fmaf(df.y, ww.y, bb.y)), 1.0f);
    }

    // ---- phase 2: bulk loads (independent -> high MLP) ----
    float2 ha[4];
    #pragma unroll
    for (int k = 0; k < 4; ++k)
        ha[k] = h2[(base >> 1) + (k << 5)];

    float fx[4], fy[4];
    #pragma unroll
    for (int k = 0; k < 4; ++k) {
        fx[k] = needx ? __ldg(h + gbasex + (k << 6)) : ha[k].x;
        fy[k] = needy ? __ldg(h + gbasey + (k << 6)) : ha[k].y;
    }

    // ---- phase 3: blend + store ----
    #pragma unroll
    for (int k = 0; k < 4; ++k) {
        float2 o;
        o.x = fmaf(cx[k], fx[k] - ha[k].x, ha[k].x);
        o.y = fmaf(cy[k], fy[k] - ha[k].y, ha[k].y);
        __stcs(out2 + (base >> 1) + (k << 5), o);
    }
}

extern "C" void kernel_launch(void* const* d_in, const int* in_sizes, int n_in,
                              void* d_out, int out_size)
{
    const float* h_a    = (const float*)d_in[0];
    const float* deltas = (const float*)d_in[1];
    const float* M      = (const float*)d_in[2];
    const float* W      = (const float*)d_in[3];
    const float* bvec   = (const float*)d_in[4];
    float* out          = (float*)d_out;

    const int blocks = NTHR / TPB;   // 8192

    temporal_decay_kernel<<<blocks, TPB>>>(
        h_a, (const float2*)h_a,
        (const float2*)deltas, (const float2*)M,
        (const float2*)W, (const float2*)bvec,
        (float2*)out);
}

// round 16
// speedup vs baseline: 1.2130x; 1.2130x over previous
#include <cuda_runtime.h>

// TemporalDecay: out = h + (1-M)*gamma*(h_fwd - h), gamma = exp(-relu(delta*W + b))
// h_fwd[b,t,j] = h[b, t-(delta-1), j], delta in {1..4} clamped to t+1, d = j % 64.
//
// R14 = R10 EXACTLY (d-pair per thread, 8 outputs via float2, uniform delta/M
// per d, stride-1 predicated gathers, full 16-load batch for MLP,
// __launch_bounds__(256,6) -> 40 regs) with ONE change:
//  * delta/M on DEFAULT cache policy (was __ldcs). Inputs h+delta+M = 101MB fit
//    L2 (126MB) and persist across graph replays; evict-first was forcing ~34MB
//    of avoidable DRAM reads per replay and putting the delta->gather-address
//    chain at DRAM latency.
//  * out keeps __stcs (write-once, never read).
// R13's regression is attributed to its (256,7) reg-cap collapsing MLP (R11
// signature), not to this policy change — this isolates the policy variable.

#define B_    32
#define T_    2048
#define D_    64
#define KD_   256
#define TPB   256
#define NTHR  (B_ * T_ * D_ / 2)   // 2,097,152 threads (one d-pair each)

__global__ __launch_bounds__(TPB, 6)
void temporal_decay_kernel(const float*  __restrict__ h,
                           const float2* __restrict__ h2,
                           const float2* __restrict__ dlt2,
                           const float2* __restrict__ m2,
                           const float2* __restrict__ w2,
                           const float2* __restrict__ b2,
                           float2* __restrict__ out2)
{
    const int i   = blockIdx.x * TPB + threadIdx.x;
    const int p   = i & 31;              // d-pair index: d = 2p
    const int row = i >> 5;              // b*T + t

    // ---- phase 1: small operands -> coefs + gather state ----
    const float2 df = dlt2[(row << 5) + p];
    const float2 mf = m2[(row << 5) + p];

    const int dix = (int)df.x, diy = (int)df.y;
    const float ax = 1.0f - mf.x, ay = 1.0f - mf.y;
    const bool needx = (mf.x == 0.0f) && (dix > 1);
    const bool needy = (mf.y == 0.0f) && (diy > 1);

    const int base   = (row << 8) + (p << 1);          // scalar index, k=0, lane d
    const int gbasex = base - ((dix - 1) << 8);        // gather bases
    const int gbasey = base + 1 - ((diy - 1) << 8);

    // coef_k = (1-m) * min(exp(-(d*W+b)), 1)
    float cx[4], cy[4];
    #pragma unroll
    for (int k = 0; k < 4; ++k) {
        const float2 ww = w2[(k << 5) + p];
        const float2 bb = b2[(k << 5) + p];
        cx[k] = ax * fminf(__expf(-fmaf(df.x, ww.x, bb.x)), 1.0f);
        cy[k] = ay * fminf(__expf(-fmaf(df.y, ww.y, bb.y)), 1.0f);
    }

    // ---- phase 2: bulk loads (independent -> high MLP) ----
    float2 ha[4];
    #pragma unroll
    for (int k = 0; k < 4; ++k)
        ha[k] = h2[(base >> 1) + (k << 5)];

    float fx[4], fy[4];
    #pragma unroll
    for (int k = 0; k < 4; ++k) {
        fx[k] = needx ? __ldg(h + gbasex + (k << 6)) : ha[k].x;
        fy[k] = needy ? __ldg(h + gbasey + (k << 6)) : ha[k].y;
    }

    // ---- phase 3: blend + store ----
    #pragma unroll
    for (int k = 0; k < 4; ++k) {
        float2 o;
        o.x = fmaf(cx[k], fx[k] - ha[k].x, ha[k].x);
        o.y = fmaf(cy[k], fy[k] - ha[k].y, ha[k].y);
        __stcs(out2 + (base >> 1) + (k << 5), o);
    }
}

extern "C" void kernel_launch(void* const* d_in, const int* in_sizes, int n_in,
                              void* d_out, int out_size)
{
    const float* h_a    = (const float*)d_in[0];
    const float* deltas = (const float*)d_in[1];
    const float* M      = (const float*)d_in[2];
    const float* W      = (const float*)d_in[3];
    const float* bvec   = (const float*)d_in[4];
    float* out          = (float*)d_out;

    const int blocks = NTHR / TPB;   // 8192

    temporal_decay_kernel<<<blocks, TPB>>>(
        h_a, (const float2*)h_a,
        (const float2*)deltas, (const float2*)M,
        (const float2*)W, (const float2*)bvec,
        (float2*)out);
}